// round 1
// baseline (speedup 1.0000x reference)
#include <cuda_runtime.h>
#include <math.h>

#define B_SZ  2
#define C_DIM 512
#define E_DIM 512
#define N_TOK 4096
#define NH    8
#define HD    64

// Scratch: Q/K/V in (B, E, N) layout = per-head (hd, N), fp32. 16 MB each.
__device__ float g_Q[B_SZ * E_DIM * N_TOK];
__device__ float g_K[B_SZ * E_DIM * N_TOK];
__device__ float g_V[B_SZ * E_DIM * N_TOK];

// ---------------------------------------------------------------------------
// Projection GEMM: R[e][n] = sum_c W[e][c] * T[c][n] + bias[e]
// T is the NCHW input viewed per-batch as (C, N) row-major (no transpose
// needed: token n = h*W + w is exactly the innermost HW index).
// Block: 64(e) x 64(n) tile, 16x16 threads, 4x4 per thread, k-chunk 16.
// ---------------------------------------------------------------------------
__global__ __launch_bounds__(256) void proj_kernel(
    const float* __restrict__ query, const float* __restrict__ key,
    const float* __restrict__ Wq, const float* __restrict__ bq,
    const float* __restrict__ Wk, const float* __restrict__ bk,
    const float* __restrict__ Wv, const float* __restrict__ bv)
{
    __shared__ float Ws[16][65];   // [c][e] (transposed store)
    __shared__ float Ts[16][64];   // [c][n]

    const int tx = threadIdx.x, ty = threadIdx.y;
    const int tid = ty * 16 + tx;
    const int n0 = blockIdx.x * 64;
    const int e0 = blockIdx.y * 64;
    const int z  = blockIdx.z;
    const int b = z / 3, p = z % 3;

    const float* T    = (p == 0 ? query : key) + (size_t)b * C_DIM * N_TOK;
    const float* W    = (p == 0 ? Wq : (p == 1 ? Wk : Wv));
    const float* bias = (p == 0 ? bq : (p == 1 ? bk : bv));
    float* Out = (p == 0 ? g_Q : (p == 1 ? g_K : g_V)) + (size_t)b * E_DIM * N_TOK;

    float acc[4][4] = {};

    for (int c0 = 0; c0 < C_DIM; c0 += 16) {
        #pragma unroll
        for (int r = 0; r < 4; r++) {
            int idx = r * 256 + tid;
            int er = idx >> 4, cc = idx & 15;
            Ws[cc][er] = W[(size_t)(e0 + er) * C_DIM + c0 + cc];
        }
        #pragma unroll
        for (int r = 0; r < 4; r++) {
            int idx = r * 256 + tid;
            int cr = idx >> 6, nc = idx & 63;
            Ts[cr][nc] = T[(size_t)(c0 + cr) * N_TOK + n0 + nc];
        }
        __syncthreads();
        #pragma unroll
        for (int k = 0; k < 16; k++) {
            float a0 = Ws[k][(ty<<2)+0], a1 = Ws[k][(ty<<2)+1];
            float a2 = Ws[k][(ty<<2)+2], a3 = Ws[k][(ty<<2)+3];
            float4 b4 = *(const float4*)&Ts[k][tx<<2];
            acc[0][0] += a0*b4.x; acc[0][1] += a0*b4.y; acc[0][2] += a0*b4.z; acc[0][3] += a0*b4.w;
            acc[1][0] += a1*b4.x; acc[1][1] += a1*b4.y; acc[1][2] += a1*b4.z; acc[1][3] += a1*b4.w;
            acc[2][0] += a2*b4.x; acc[2][1] += a2*b4.y; acc[2][2] += a2*b4.z; acc[2][3] += a2*b4.w;
            acc[3][0] += a3*b4.x; acc[3][1] += a3*b4.y; acc[3][2] += a3*b4.z; acc[3][3] += a3*b4.w;
        }
        __syncthreads();
    }

    #pragma unroll
    for (int i = 0; i < 4; i++) {
        int e = e0 + (ty<<2) + i;
        float bb = bias[e];
        float4 v = make_float4(acc[i][0] + bb, acc[i][1] + bb,
                               acc[i][2] + bb, acc[i][3] + bb);
        *(float4*)(Out + (size_t)e * N_TOK + n0 + (tx<<2)) = v;
    }
}

// ---------------------------------------------------------------------------
// Flash attention (fp32 SIMT). Block = one (b, h, 64-query tile).
// Q/K/V per head are (hd=64, N) d-major. S computed as Q^T K per 64x64 tile,
// online softmax in registers, P@V accumulated via smem-staged P.
// Epilogue writes out[b, h*64+d, n] directly (smem transpose for coalescing).
// ---------------------------------------------------------------------------
__global__ __launch_bounds__(256) void attn_kernel(float* __restrict__ out)
{
    extern __shared__ float smem[];
    float* Qs  = smem;          // [64][64]  [d][i]
    float* KPs = smem + 4096;   // [64][64]  K:[d][j] -> P:[i][j] -> O:[d][i]
    float* Vs  = smem + 8192;   // [64][65]  [d][j]   (pad: 2-way max conflict)

    const int tx = threadIdx.x, ty = threadIdx.y;
    const int tid = ty * 16 + tx;
    const int it = gridDim.x - 1 - blockIdx.x;   // heavy tiles launch first
    const int i0 = it * 64;
    const int h = blockIdx.y;
    const int b = blockIdx.z;

    const float* Qg = g_Q + ((size_t)b * E_DIM + h * HD) * N_TOK;
    const float* Kg = g_K + ((size_t)b * E_DIM + h * HD) * N_TOK;
    const float* Vg = g_V + ((size_t)b * E_DIM + h * HD) * N_TOK;

    #pragma unroll
    for (int r = 0; r < 16; r++) {
        int idx = r * 256 + tid;
        int d = idx >> 6, x = idx & 63;
        Qs[d * 64 + x] = Qg[(size_t)d * N_TOK + i0 + x];
    }

    float m[4], l[4], o[4][4];
    #pragma unroll
    for (int ii = 0; ii < 4; ii++) {
        m[ii] = -1e30f; l[ii] = 0.f;
        #pragma unroll
        for (int dd = 0; dd < 4; dd++) o[ii][dd] = 0.f;
    }

    const float scale = 0.125f;  // 1/sqrt(64)

    for (int jt = 0; jt <= it; jt++) {
        const int j0 = jt * 64;
        __syncthreads();   // prev PV done; safe to overwrite KPs/Vs
        #pragma unroll
        for (int r = 0; r < 16; r++) {
            int idx = r * 256 + tid;
            int d = idx >> 6, x = idx & 63;
            KPs[d * 64 + x] = Kg[(size_t)d * N_TOK + j0 + x];
            Vs[d * 65 + x]  = Vg[(size_t)d * N_TOK + j0 + x];
        }
        __syncthreads();

        // S = Q^T K  (64x64 tile, 4x4 per thread)
        float s[4][4] = {};
        #pragma unroll 16
        for (int d = 0; d < 64; d++) {
            float4 qa = *(const float4*)&Qs[d * 64 + (ty<<2)];
            float4 kb = *(const float4*)&KPs[d * 64 + (tx<<2)];
            s[0][0] += qa.x*kb.x; s[0][1] += qa.x*kb.y; s[0][2] += qa.x*kb.z; s[0][3] += qa.x*kb.w;
            s[1][0] += qa.y*kb.x; s[1][1] += qa.y*kb.y; s[1][2] += qa.y*kb.z; s[1][3] += qa.y*kb.w;
            s[2][0] += qa.z*kb.x; s[2][1] += qa.z*kb.y; s[2][2] += qa.z*kb.z; s[2][3] += qa.z*kb.w;
            s[3][0] += qa.w*kb.x; s[3][1] += qa.w*kb.y; s[3][2] += qa.w*kb.z; s[3][3] += qa.w*kb.w;
        }

        // scale + causal mask (only the diagonal tile needs masking)
        #pragma unroll
        for (int ii = 0; ii < 4; ii++)
            #pragma unroll
            for (int jj = 0; jj < 4; jj++)
                s[ii][jj] *= scale;
        if (jt == it) {
            #pragma unroll
            for (int ii = 0; ii < 4; ii++) {
                int qi = i0 + (ty<<2) + ii;
                #pragma unroll
                for (int jj = 0; jj < 4; jj++) {
                    int kj = j0 + (tx<<2) + jj;
                    if (kj > qi) s[ii][jj] = -1e9f;
                }
            }
        }

        // online softmax update (row stats via shfl over tx lanes)
        #pragma unroll
        for (int ii = 0; ii < 4; ii++) {
            float mt = fmaxf(fmaxf(s[ii][0], s[ii][1]), fmaxf(s[ii][2], s[ii][3]));
            #pragma unroll
            for (int off = 1; off < 16; off <<= 1)
                mt = fmaxf(mt, __shfl_xor_sync(0xffffffffu, mt, off));
            float mn = fmaxf(m[ii], mt);
            float alpha = __expf(m[ii] - mn);
            m[ii] = mn;
            #pragma unroll
            for (int jj = 0; jj < 4; jj++) s[ii][jj] = __expf(s[ii][jj] - mn);
            float rs = s[ii][0] + s[ii][1] + s[ii][2] + s[ii][3];
            #pragma unroll
            for (int off = 1; off < 16; off <<= 1)
                rs += __shfl_xor_sync(0xffffffffu, rs, off);
            l[ii] = l[ii] * alpha + rs;
            #pragma unroll
            for (int dd = 0; dd < 4; dd++) o[ii][dd] *= alpha;
        }

        __syncthreads();   // all K reads done; KPs becomes P
        #pragma unroll
        for (int ii = 0; ii < 4; ii++)
            *(float4*)&KPs[((ty<<2)+ii) * 64 + (tx<<2)] =
                make_float4(s[ii][0], s[ii][1], s[ii][2], s[ii][3]);
        __syncthreads();

        // O += P @ V   (o[i][d], d = tx*4+dd)
        #pragma unroll 4
        for (int jb = 0; jb < 64; jb += 4) {
            float4 p4[4];
            #pragma unroll
            for (int ii = 0; ii < 4; ii++)
                p4[ii] = *(const float4*)&KPs[((ty<<2)+ii) * 64 + jb];
            #pragma unroll
            for (int dd = 0; dd < 4; dd++) {
                const float* vrow = &Vs[((tx<<2)+dd) * 65 + jb];
                float v0 = vrow[0], v1 = vrow[1], v2 = vrow[2], v3 = vrow[3];
                #pragma unroll
                for (int ii = 0; ii < 4; ii++)
                    o[ii][dd] += p4[ii].x*v0 + p4[ii].y*v1 + p4[ii].z*v2 + p4[ii].w*v3;
            }
        }
    }

    // normalize, transpose-stage into smem, coalesced global write
    __syncthreads();
    #pragma unroll
    for (int ii = 0; ii < 4; ii++) {
        float inv = 1.f / l[ii];
        #pragma unroll
        for (int dd = 0; dd < 4; dd++)
            KPs[((tx<<2)+dd) * 64 + (ty<<2) + ii] = o[ii][dd] * inv;
    }
    __syncthreads();

    float* Og = out + ((size_t)b * E_DIM + h * HD) * N_TOK + i0;
    #pragma unroll
    for (int r = 0; r < 16; r++) {
        int idx = r * 256 + tid;
        int d = idx >> 6, x = idx & 63;
        Og[(size_t)d * N_TOK + x] = KPs[d * 64 + x];
    }
}

extern "C" void kernel_launch(void* const* d_in, const int* in_sizes, int n_in,
                              void* d_out, int out_size) {
    const float* query = (const float*)d_in[0];
    const float* key   = (const float*)d_in[1];
    const float* Wq    = (const float*)d_in[2];
    const float* bq    = (const float*)d_in[3];
    const float* Wk    = (const float*)d_in[4];
    const float* bk    = (const float*)d_in[5];
    const float* Wv    = (const float*)d_in[6];
    const float* bv    = (const float*)d_in[7];
    float* out = (float*)d_out;

    dim3 blk(16, 16);
    proj_kernel<<<dim3(N_TOK / 64, E_DIM / 64, 3 * B_SZ), blk>>>(
        query, key, Wq, bq, Wk, bk, Wv, bv);

    const int smem_bytes = (4096 + 4096 + 64 * 65) * (int)sizeof(float);  // 49408
    cudaFuncSetAttribute(attn_kernel, cudaFuncAttributeMaxDynamicSharedMemorySize,
                         smem_bytes);
    attn_kernel<<<dim3(N_TOK / 64, NH, B_SZ), blk, smem_bytes>>>(out);
}

// round 2
// speedup vs baseline: 2.1598x; 2.1598x over previous
#include <cuda_runtime.h>
#include <math.h>
#include <stdint.h>

#define B_SZ  2
#define C_DIM 512
#define E_DIM 512
#define N_TOK 4096
#define NH    8
#define HD    64

// Scratch: Q/K/V in (B, E, N) layout = per-head (hd, N), fp32(tf32-rounded bits).
__device__ float g_Q[B_SZ * E_DIM * N_TOK];
__device__ float g_K[B_SZ * E_DIM * N_TOK];
__device__ float g_V[B_SZ * E_DIM * N_TOK];

__device__ __forceinline__ uint32_t f2tf(float f) {
    uint32_t r;
    asm("cvt.rna.tf32.f32 %0, %1;" : "=r"(r) : "f"(f));
    return r;
}
__device__ __forceinline__ float f2tff(float f) {
    return __uint_as_float(f2tf(f));
}
__device__ __forceinline__ void mma_tf32(float* d, uint32_t a0, uint32_t a1,
                                         uint32_t a2, uint32_t a3,
                                         uint32_t b0, uint32_t b1) {
    asm volatile(
        "mma.sync.aligned.m16n8k8.row.col.f32.tf32.tf32.f32 "
        "{%0,%1,%2,%3}, {%4,%5,%6,%7}, {%8,%9}, {%0,%1,%2,%3};"
        : "+f"(d[0]), "+f"(d[1]), "+f"(d[2]), "+f"(d[3])
        : "r"(a0), "r"(a1), "r"(a2), "r"(a3), "r"(b0), "r"(b1));
}

// ---------------------------------------------------------------------------
// Projection GEMM (tf32 mma): R[e][n] = W[e][:].T[:][n] + bias[e]
// Tile: 64(e) x 128(n), K-chunk 32. 8 warps: warp = (wm = w&1)*32 rows x
// (wn = w>>1)*32 cols; per warp 2 m-tiles x 4 n-tiles of m16n8k8.
// ---------------------------------------------------------------------------
__global__ __launch_bounds__(256) void proj_kernel(
    const float* __restrict__ query, const float* __restrict__ key,
    const float* __restrict__ Wq, const float* __restrict__ bq,
    const float* __restrict__ Wk, const float* __restrict__ bk,
    const float* __restrict__ Wv, const float* __restrict__ bv)
{
    __shared__ float As[64 * 33];    // [e][c]  row-major A
    __shared__ float Bs[128 * 33];   // [n][c]  col-major B (k contiguous)

    const int tid = threadIdx.x;
    const int w = tid >> 5, lane = tid & 31;
    const int g = lane >> 2, t = lane & 3;
    const int wm = w & 1, wn = w >> 1;

    const int n0 = blockIdx.x * 128;
    const int e0 = blockIdx.y * 64;
    const int z  = blockIdx.z;
    const int b = z / 3, p = z % 3;

    const float* T    = (p == 0 ? query : key) + (size_t)b * C_DIM * N_TOK;
    const float* W    = (p == 0 ? Wq : (p == 1 ? Wk : Wv));
    const float* bias = (p == 0 ? bq : (p == 1 ? bk : bv));
    float* Out = (p == 0 ? g_Q : (p == 1 ? g_K : g_V)) + (size_t)b * E_DIM * N_TOK;

    float acc[2][4][4] = {};

    for (int c0 = 0; c0 < C_DIM; c0 += 32) {
        __syncthreads();
        #pragma unroll
        for (int r = 0; r < 8; r++) {           // A: 64x32
            int idx = r * 256 + tid;
            int e = idx >> 5, c = idx & 31;
            As[e * 33 + c] = f2tff(W[(size_t)(e0 + e) * C_DIM + c0 + c]);
        }
        #pragma unroll
        for (int r = 0; r < 16; r++) {          // B: 32x128 -> [n][c]
            int idx = r * 256 + tid;
            int c = idx >> 7, n = idx & 127;
            Bs[n * 33 + c] = f2tff(T[(size_t)(c0 + c) * N_TOK + n0 + n]);
        }
        __syncthreads();

        #pragma unroll
        for (int kt = 0; kt < 4; kt++) {
            uint32_t a[2][4];
            #pragma unroll
            for (int mi = 0; mi < 2; mi++) {
                int rbase = (wm * 32 + mi * 16 + g) * 33 + kt * 8 + t;
                a[mi][0] = __float_as_uint(As[rbase]);
                a[mi][1] = __float_as_uint(As[rbase + 8 * 33]);
                a[mi][2] = __float_as_uint(As[rbase + 4]);
                a[mi][3] = __float_as_uint(As[rbase + 8 * 33 + 4]);
            }
            #pragma unroll
            for (int nt = 0; nt < 4; nt++) {
                int bbase = (wn * 32 + nt * 8 + g) * 33 + kt * 8 + t;
                uint32_t b0 = __float_as_uint(Bs[bbase]);
                uint32_t b1 = __float_as_uint(Bs[bbase + 4]);
                mma_tf32(acc[0][nt], a[0][0], a[0][1], a[0][2], a[0][3], b0, b1);
                mma_tf32(acc[1][nt], a[1][0], a[1][1], a[1][2], a[1][3], b0, b1);
            }
        }
    }

    #pragma unroll
    for (int mi = 0; mi < 2; mi++) {
        int e_lo = e0 + wm * 32 + mi * 16 + g;
        float b_lo = bias[e_lo], b_hi = bias[e_lo + 8];
        #pragma unroll
        for (int nt = 0; nt < 4; nt++) {
            int n = n0 + wn * 32 + nt * 8 + t * 2;
            *(float2*)(Out + (size_t)e_lo * N_TOK + n) =
                make_float2(acc[mi][nt][0] + b_lo, acc[mi][nt][1] + b_lo);
            *(float2*)(Out + (size_t)(e_lo + 8) * N_TOK + n) =
                make_float2(acc[mi][nt][2] + b_hi, acc[mi][nt][3] + b_hi);
        }
    }
}

// ---------------------------------------------------------------------------
// Flash attention, tf32 mma. Block = (b, h, 128-query tile), 8 warps.
// Warp w owns query rows [16w, 16w+16). Bc = 64 keys per iteration.
// S = Q K^T via mma (A=Qs[i][d], B=Ks[j][d]); online softmax on accums;
// P staged per-warp to smem; O += P V via mma (A=Ps[i][j], B=Vs[d][j]).
// ---------------------------------------------------------------------------
__global__ __launch_bounds__(256, 2) void attn_kernel(float* __restrict__ out)
{
    extern __shared__ float smem[];
    float* Qs = smem;                 // [128][65]  A for S
    float* Ks = Qs + 128 * 65;        // [64][65]   B for S  ([j][d])
    float* Vs = Ks + 64 * 65;         // [64][65]   B for PV ([d][j])
    float* Ps = Vs + 64 * 65;         // [128][68]  P ([i][j]); epilogue: O^T [64][130]

    const int tid = threadIdx.x;
    const int w = tid >> 5, lane = tid & 31;
    const int g = lane >> 2, t = lane & 3;

    const int it = gridDim.x - 1 - blockIdx.x;   // heavy tiles first
    const int i0 = it * 128;
    const int h = blockIdx.y, b = blockIdx.z;

    const float* Qg = g_Q + ((size_t)b * E_DIM + h * HD) * N_TOK;
    const float* Kg = g_K + ((size_t)b * E_DIM + h * HD) * N_TOK;
    const float* Vg = g_V + ((size_t)b * E_DIM + h * HD) * N_TOK;

    // stage Q (128 x 64), transpose to [i][d], tf32-round
    #pragma unroll
    for (int r = 0; r < 32; r++) {
        int idx = r * 256 + tid;
        int d = idx >> 7, i = idx & 127;
        Qs[i * 65 + d] = f2tff(Qg[(size_t)d * N_TOK + i0 + i]);
    }

    float m0 = -1e30f, m1 = -1e30f, l0 = 0.f, l1 = 0.f;
    float o[8][4] = {};
    const float scale = 0.125f;  // 1/sqrt(64)
    const int njt = 2 * it + 2;

    for (int jt = 0; jt < njt; jt++) {
        const int j0 = jt * 64;
        __syncthreads();   // Q staged (first iter) / prev K,V reads done
        #pragma unroll
        for (int r = 0; r < 16; r++) {
            int idx = r * 256 + tid;
            int d = idx >> 6, j = idx & 63;
            float kv = Kg[(size_t)d * N_TOK + j0 + j];
            float vv = Vg[(size_t)d * N_TOK + j0 + j];
            Ks[j * 65 + d] = f2tff(kv);
            Vs[d * 65 + j] = f2tff(vv);
        }
        __syncthreads();

        // ---- S = Q K^T (16 x 64 per warp) ----
        float s[8][4] = {};
        #pragma unroll
        for (int kt = 0; kt < 8; kt++) {
            int abase = (16 * w + g) * 65 + kt * 8 + t;
            uint32_t a0 = __float_as_uint(Qs[abase]);
            uint32_t a1 = __float_as_uint(Qs[abase + 8 * 65]);
            uint32_t a2 = __float_as_uint(Qs[abase + 4]);
            uint32_t a3 = __float_as_uint(Qs[abase + 8 * 65 + 4]);
            #pragma unroll
            for (int nt = 0; nt < 8; nt++) {
                int bbase = (nt * 8 + g) * 65 + kt * 8 + t;
                uint32_t b0 = __float_as_uint(Ks[bbase]);
                uint32_t b1 = __float_as_uint(Ks[bbase + 4]);
                mma_tf32(s[nt], a0, a1, a2, a3, b0, b1);
            }
        }

        // scale + causal mask (only the two diagonal-region tiles)
        #pragma unroll
        for (int nt = 0; nt < 8; nt++) {
            s[nt][0] *= scale; s[nt][1] *= scale;
            s[nt][2] *= scale; s[nt][3] *= scale;
        }
        if (jt >= 2 * it) {
            int r_lo = i0 + 16 * w + g, r_hi = r_lo + 8;
            #pragma unroll
            for (int nt = 0; nt < 8; nt++) {
                int c = j0 + nt * 8 + t * 2;
                if (c     > r_lo) s[nt][0] = -1e9f;
                if (c + 1 > r_lo) s[nt][1] = -1e9f;
                if (c     > r_hi) s[nt][2] = -1e9f;
                if (c + 1 > r_hi) s[nt][3] = -1e9f;
            }
        }

        // ---- online softmax (rows g and g+8 of this warp) ----
        float mt0 = -1e30f, mt1 = -1e30f;
        #pragma unroll
        for (int nt = 0; nt < 8; nt++) {
            mt0 = fmaxf(mt0, fmaxf(s[nt][0], s[nt][1]));
            mt1 = fmaxf(mt1, fmaxf(s[nt][2], s[nt][3]));
        }
        mt0 = fmaxf(mt0, __shfl_xor_sync(0xffffffffu, mt0, 1));
        mt0 = fmaxf(mt0, __shfl_xor_sync(0xffffffffu, mt0, 2));
        mt1 = fmaxf(mt1, __shfl_xor_sync(0xffffffffu, mt1, 1));
        mt1 = fmaxf(mt1, __shfl_xor_sync(0xffffffffu, mt1, 2));

        float mn0 = fmaxf(m0, mt0), mn1 = fmaxf(m1, mt1);
        float al0 = __expf(m0 - mn0), al1 = __expf(m1 - mn1);
        m0 = mn0; m1 = mn1;

        float rs0 = 0.f, rs1 = 0.f;
        #pragma unroll
        for (int nt = 0; nt < 8; nt++) {
            s[nt][0] = __expf(s[nt][0] - mn0);
            s[nt][1] = __expf(s[nt][1] - mn0);
            s[nt][2] = __expf(s[nt][2] - mn1);
            s[nt][3] = __expf(s[nt][3] - mn1);
            rs0 += s[nt][0] + s[nt][1];
            rs1 += s[nt][2] + s[nt][3];
        }
        rs0 += __shfl_xor_sync(0xffffffffu, rs0, 1);
        rs0 += __shfl_xor_sync(0xffffffffu, rs0, 2);
        rs1 += __shfl_xor_sync(0xffffffffu, rs1, 1);
        rs1 += __shfl_xor_sync(0xffffffffu, rs1, 2);
        l0 = l0 * al0 + rs0;
        l1 = l1 * al1 + rs1;
        #pragma unroll
        for (int nt = 0; nt < 8; nt++) {
            o[nt][0] *= al0; o[nt][1] *= al0;
            o[nt][2] *= al1; o[nt][3] *= al1;
        }

        // ---- stage P (per-warp rows; no block sync needed) ----
        #pragma unroll
        for (int nt = 0; nt < 8; nt++) {
            int c = nt * 8 + t * 2;
            *(float2*)&Ps[(16 * w + g) * 68 + c] =
                make_float2(f2tff(s[nt][0]), f2tff(s[nt][1]));
            *(float2*)&Ps[(16 * w + 8 + g) * 68 + c] =
                make_float2(f2tff(s[nt][2]), f2tff(s[nt][3]));
        }
        __syncwarp();

        // ---- O += P V (16 x 64 per warp) ----
        #pragma unroll
        for (int kt = 0; kt < 8; kt++) {
            int abase = (16 * w + g) * 68 + kt * 8 + t;
            uint32_t a0 = __float_as_uint(Ps[abase]);
            uint32_t a1 = __float_as_uint(Ps[abase + 8 * 68]);
            uint32_t a2 = __float_as_uint(Ps[abase + 4]);
            uint32_t a3 = __float_as_uint(Ps[abase + 8 * 68 + 4]);
            #pragma unroll
            for (int nt = 0; nt < 8; nt++) {
                int bbase = (nt * 8 + g) * 65 + kt * 8 + t;
                uint32_t b0 = __float_as_uint(Vs[bbase]);
                uint32_t b1 = __float_as_uint(Vs[bbase + 4]);
                mma_tf32(o[nt], a0, a1, a2, a3, b0, b1);
            }
        }
    }

    // ---- epilogue: normalize, transpose via smem, coalesced store ----
    __syncthreads();   // everyone done with Ps as P; reuse as O^T [d][i] ld=130
    float inv0 = 1.f / l0, inv1 = 1.f / l1;
    #pragma unroll
    for (int nt = 0; nt < 8; nt++) {
        int d = nt * 8 + t * 2;
        Ps[(d)     * 130 + 16 * w + g]     = o[nt][0] * inv0;
        Ps[(d + 1) * 130 + 16 * w + g]     = o[nt][1] * inv0;
        Ps[(d)     * 130 + 16 * w + 8 + g] = o[nt][2] * inv1;
        Ps[(d + 1) * 130 + 16 * w + 8 + g] = o[nt][3] * inv1;
    }
    __syncthreads();

    float* Og = out + ((size_t)b * E_DIM + h * HD) * N_TOK + i0;
    #pragma unroll
    for (int r = 0; r < 32; r++) {
        int idx = r * 256 + tid;
        int d = idx >> 7, i = idx & 127;
        Og[(size_t)d * N_TOK + i] = Ps[d * 130 + i];
    }
}

extern "C" void kernel_launch(void* const* d_in, const int* in_sizes, int n_in,
                              void* d_out, int out_size) {
    const float* query = (const float*)d_in[0];
    const float* key   = (const float*)d_in[1];
    const float* Wq    = (const float*)d_in[2];
    const float* bq    = (const float*)d_in[3];
    const float* Wk    = (const float*)d_in[4];
    const float* bk    = (const float*)d_in[5];
    const float* Wv    = (const float*)d_in[6];
    const float* bv    = (const float*)d_in[7];
    float* out = (float*)d_out;

    proj_kernel<<<dim3(N_TOK / 128, E_DIM / 64, 3 * B_SZ), 256>>>(
        query, key, Wq, bq, Wk, bk, Wv, bv);

    const int smem_bytes = (128 * 65 + 64 * 65 + 64 * 65 + 128 * 68) *
                           (int)sizeof(float);   // 101376
    cudaFuncSetAttribute(attn_kernel, cudaFuncAttributeMaxDynamicSharedMemorySize,
                         smem_bytes);
    attn_kernel<<<dim3(N_TOK / 128, NH, B_SZ), 256, smem_bytes>>>(out);
}

// round 4
// speedup vs baseline: 4.7973x; 2.2212x over previous
#include <cuda_runtime.h>
#include <math.h>
#include <stdint.h>

#define B_SZ  2
#define C_DIM 512
#define E_DIM 512
#define N_TOK 4096
#define NH    8
#define HD    64

// Scratch (all __device__ globals; no allocation).
__device__ float g_Q[B_SZ * E_DIM * N_TOK];
__device__ float g_K[B_SZ * E_DIM * N_TOK];
__device__ float g_V[B_SZ * E_DIM * N_TOK];
// tf32-rounded copies of proj inputs (cp.async feeds mma directly from these).
__device__ float g_TQ[B_SZ * C_DIM * N_TOK];
__device__ float g_TK[B_SZ * C_DIM * N_TOK];
__device__ float g_W[3 * E_DIM * C_DIM];

__device__ __forceinline__ float f2tff(float f) {
    uint32_t r;
    asm("cvt.rna.tf32.f32 %0, %1;" : "=r"(r) : "f"(f));
    return __uint_as_float(r);
}
__device__ __forceinline__ void mma_tf32(float* d, uint32_t a0, uint32_t a1,
                                         uint32_t a2, uint32_t a3,
                                         uint32_t b0, uint32_t b1) {
    asm volatile(
        "mma.sync.aligned.m16n8k8.row.col.f32.tf32.tf32.f32 "
        "{%0,%1,%2,%3}, {%4,%5,%6,%7}, {%8,%9}, {%0,%1,%2,%3};"
        : "+f"(d[0]), "+f"(d[1]), "+f"(d[2]), "+f"(d[3])
        : "r"(a0), "r"(a1), "r"(a2), "r"(a3), "r"(b0), "r"(b1));
}
__device__ __forceinline__ void cp16(float* dst, const float* src) {
    uint32_t d = (uint32_t)__cvta_generic_to_shared(dst);
    asm volatile("cp.async.cg.shared.global [%0], [%1], 16;"
                 :: "r"(d), "l"(src) : "memory");
}
__device__ __forceinline__ void cp_commit() {
    asm volatile("cp.async.commit_group;" ::: "memory");
}
__device__ __forceinline__ void cp_wait1() {
    asm volatile("cp.async.wait_group 1;" ::: "memory");
}

// ---------------------------------------------------------------------------
// tf32 rounding copy (vectorized, grid-stride). n must be /4.
// ---------------------------------------------------------------------------
__global__ void round_kernel(float* __restrict__ dst, const float* __restrict__ src,
                             int n4) {
    int i = blockIdx.x * blockDim.x + threadIdx.x;
    int stride = gridDim.x * blockDim.x;
    for (; i < n4; i += stride) {
        float4 v = ((const float4*)src)[i];
        v.x = f2tff(v.x); v.y = f2tff(v.y); v.z = f2tff(v.z); v.w = f2tff(v.w);
        ((float4*)dst)[i] = v;
    }
}

// ---------------------------------------------------------------------------
// Projection GEMM (tf32 mma, cp.async double-buffered; inputs pre-rounded).
// R[e][n] = sum_c W[e][c] * T[c][n] + bias[e], output tf32-rounded.
// Tile 64(e) x 128(n), K-chunk 32. A=[e][c] ld 36, B=[c][n] ld 136.
// ---------------------------------------------------------------------------
__global__ __launch_bounds__(256, 2) void proj_kernel(
    const float* __restrict__ bq, const float* __restrict__ bk,
    const float* __restrict__ bv)
{
    extern __shared__ float sm[];
    float* As = sm;            // 2 x [64][36]  = 4608 floats
    float* Bs = sm + 4608;     // 2 x [32][136] = 8704 floats

    const int tid = threadIdx.x;
    const int w = tid >> 5, lane = tid & 31;
    const int g = lane >> 2, t = lane & 3;
    const int wm = w & 1, wn = w >> 1;

    const int n0 = blockIdx.x * 128;
    const int e0 = blockIdx.y * 64;
    const int z  = blockIdx.z;
    const int b = z / 3, p = z % 3;

    const float* T    = (p == 0 ? g_TQ : g_TK) + (size_t)b * C_DIM * N_TOK;
    const float* W    = g_W + (size_t)p * E_DIM * C_DIM;
    const float* bias = (p == 0 ? bq : (p == 1 ? bk : bv));
    float* Out = (p == 0 ? g_Q : (p == 1 ? g_K : g_V)) + (size_t)b * E_DIM * N_TOK;

    const int NSTEP = C_DIM / 32;   // 16

    auto stage = [&](int s_iter) {
        if (s_iter < NSTEP) {
            int s = s_iter & 1;
            int c0 = s_iter * 32;
            #pragma unroll
            for (int r = 0; r < 2; r++) {        // A: 64 x 32
                int c = r * 256 + tid;
                int e = c >> 3, cc = c & 7;
                cp16(&As[s * 2304 + e * 36 + cc * 4],
                     W + (size_t)(e0 + e) * C_DIM + c0 + cc * 4);
            }
            #pragma unroll
            for (int r = 0; r < 4; r++) {        // B: 32 x 128
                int c = r * 256 + tid;
                int cr = c >> 5, nc = c & 31;
                cp16(&Bs[s * 4352 + cr * 136 + nc * 4],
                     T + (size_t)(c0 + cr) * N_TOK + n0 + nc * 4);
            }
        }
        cp_commit();
    };

    stage(0);

    float acc[2][4][4] = {};

    for (int ks = 0; ks < NSTEP; ks++) {
        __syncthreads();          // prior reads of buffer (ks+1)&1 done
        stage(ks + 1);
        cp_wait1();
        __syncthreads();

        const float* A = As + (ks & 1) * 2304;
        const float* Bt = Bs + (ks & 1) * 4352;

        #pragma unroll
        for (int kt = 0; kt < 4; kt++) {
            uint32_t a[2][4];
            #pragma unroll
            for (int mi = 0; mi < 2; mi++) {
                int ab = (wm * 32 + mi * 16 + g) * 36 + kt * 8 + t;
                a[mi][0] = __float_as_uint(A[ab]);
                a[mi][1] = __float_as_uint(A[ab + 8 * 36]);
                a[mi][2] = __float_as_uint(A[ab + 4]);
                a[mi][3] = __float_as_uint(A[ab + 8 * 36 + 4]);
            }
            #pragma unroll
            for (int nt = 0; nt < 4; nt++) {
                int bb = (kt * 8 + t) * 136 + wn * 32 + nt * 8 + g;
                uint32_t b0 = __float_as_uint(Bt[bb]);
                uint32_t b1 = __float_as_uint(Bt[bb + 4 * 136]);
                mma_tf32(acc[0][nt], a[0][0], a[0][1], a[0][2], a[0][3], b0, b1);
                mma_tf32(acc[1][nt], a[1][0], a[1][1], a[1][2], a[1][3], b0, b1);
            }
        }
    }

    #pragma unroll
    for (int mi = 0; mi < 2; mi++) {
        int e_lo = e0 + wm * 32 + mi * 16 + g;
        float b_lo = bias[e_lo], b_hi = bias[e_lo + 8];
        #pragma unroll
        for (int nt = 0; nt < 4; nt++) {
            int n = n0 + wn * 32 + nt * 8 + t * 2;
            *(float2*)(Out + (size_t)e_lo * N_TOK + n) =
                make_float2(f2tff(acc[mi][nt][0] + b_lo), f2tff(acc[mi][nt][1] + b_lo));
            *(float2*)(Out + (size_t)(e_lo + 8) * N_TOK + n) =
                make_float2(f2tff(acc[mi][nt][2] + b_hi), f2tff(acc[mi][nt][3] + b_hi));
        }
    }
}

// ---------------------------------------------------------------------------
// Flash attention, tf32 mma, cp.async double-buffered K/V (gmem is tf32 bits).
// Block = (b, h, 128-query tile), 8 warps; warp owns 16 query rows. Bc=32.
// Layouts: Q [d=64][i=128] ld136, K [d][j=32] ld40, V [d][j] ld36,
// P [i=128][j] ld36. All fragment LDS conflict-free by stride choice.
// ---------------------------------------------------------------------------
__global__ __launch_bounds__(256, 2) void attn_kernel(float* __restrict__ out)
{
    extern __shared__ float sm[];
    float* Ks = sm;              // 2 x [64][40] = 5120
    float* Vs = sm + 5120;       // 2 x [64][36] = 4608
    float* Qs = sm + 9728;       // [64][136]    = 8704  (epilogue: O^T)
    float* Ps = sm + 18432;      // [128][36]    = 4608

    const int tid = threadIdx.x;
    const int w = tid >> 5, lane = tid & 31;
    const int g = lane >> 2, t = lane & 3;
    const int ri = 16 * w + g;

    const int it = gridDim.x - 1 - blockIdx.x;   // heavy tiles first
    const int i0 = it * 128;
    const int h = blockIdx.y, b = blockIdx.z;

    const float* Qg = g_Q + ((size_t)b * E_DIM + h * HD) * N_TOK;
    const float* Kg = g_K + ((size_t)b * E_DIM + h * HD) * N_TOK;
    const float* Vg = g_V + ((size_t)b * E_DIM + h * HD) * N_TOK;

    const int njt = 4 * it + 4;

    auto stage = [&](int jt) {
        if (jt < njt) {
            int s = jt & 1;
            int j0 = jt * 32;
            #pragma unroll
            for (int r = 0; r < 2; r++) {        // K: 64 x 32
                int c = r * 256 + tid;
                int d = c >> 3, jc = c & 7;
                cp16(&Ks[s * 2560 + d * 40 + jc * 4],
                     Kg + (size_t)d * N_TOK + j0 + jc * 4);
            }
            #pragma unroll
            for (int r = 0; r < 2; r++) {        // V: 64 x 32
                int c = r * 256 + tid;
                int d = c >> 3, jc = c & 7;
                cp16(&Vs[s * 2304 + d * 36 + jc * 4],
                     Vg + (size_t)d * N_TOK + j0 + jc * 4);
            }
        }
        cp_commit();
    };

    stage(0);
    // Q staging (plain loads; latency overlaps with the cp.async above)
    #pragma unroll
    for (int r = 0; r < 32; r++) {
        int idx = r * 256 + tid;
        int d = idx >> 7, i = idx & 127;
        Qs[d * 136 + i] = Qg[(size_t)d * N_TOK + i0 + i];
    }

    float m0 = -1e30f, m1 = -1e30f, l0 = 0.f, l1 = 0.f;
    float o[8][4] = {};
    const float scale = 0.125f;  // 1/sqrt(64)

    for (int jt = 0; jt < njt; jt++) {
        __syncthreads();          // reads of buffer (jt+1)&1 (iter jt-1) done; Q visible
        stage(jt + 1);
        cp_wait1();
        __syncthreads();

        const float* K = Ks + (jt & 1) * 2560;
        const float* V = Vs + (jt & 1) * 2304;
        const int j0 = jt * 32;

        // ---- S = Q K^T (16 x 32 per warp) ----
        float s[4][4] = {};
        #pragma unroll
        for (int kt = 0; kt < 8; kt++) {
            int ab = (kt * 8 + t) * 136 + ri;
            uint32_t a0 = __float_as_uint(Qs[ab]);
            uint32_t a1 = __float_as_uint(Qs[ab + 8]);
            uint32_t a2 = __float_as_uint(Qs[ab + 4 * 136]);
            uint32_t a3 = __float_as_uint(Qs[ab + 4 * 136 + 8]);
            #pragma unroll
            for (int nt = 0; nt < 4; nt++) {
                int bb = (kt * 8 + t) * 40 + nt * 8 + g;
                uint32_t b0 = __float_as_uint(K[bb]);
                uint32_t b1 = __float_as_uint(K[bb + 4 * 40]);
                mma_tf32(s[nt], a0, a1, a2, a3, b0, b1);
            }
        }

        // scale + causal mask (diagonal-region tiles only)
        #pragma unroll
        for (int nt = 0; nt < 4; nt++) {
            s[nt][0] *= scale; s[nt][1] *= scale;
            s[nt][2] *= scale; s[nt][3] *= scale;
        }
        if (jt >= 4 * it) {
            int r_lo = i0 + ri, r_hi = r_lo + 8;
            #pragma unroll
            for (int nt = 0; nt < 4; nt++) {
                int c = j0 + nt * 8 + t * 2;
                if (c     > r_lo) s[nt][0] = -1e9f;
                if (c + 1 > r_lo) s[nt][1] = -1e9f;
                if (c     > r_hi) s[nt][2] = -1e9f;
                if (c + 1 > r_hi) s[nt][3] = -1e9f;
            }
        }

        // ---- online softmax ----
        float mt0 = -1e30f, mt1 = -1e30f;
        #pragma unroll
        for (int nt = 0; nt < 4; nt++) {
            mt0 = fmaxf(mt0, fmaxf(s[nt][0], s[nt][1]));
            mt1 = fmaxf(mt1, fmaxf(s[nt][2], s[nt][3]));
        }
        mt0 = fmaxf(mt0, __shfl_xor_sync(0xffffffffu, mt0, 1));
        mt0 = fmaxf(mt0, __shfl_xor_sync(0xffffffffu, mt0, 2));
        mt1 = fmaxf(mt1, __shfl_xor_sync(0xffffffffu, mt1, 1));
        mt1 = fmaxf(mt1, __shfl_xor_sync(0xffffffffu, mt1, 2));

        float mn0 = fmaxf(m0, mt0), mn1 = fmaxf(m1, mt1);
        float al0 = __expf(m0 - mn0), al1 = __expf(m1 - mn1);
        m0 = mn0; m1 = mn1;

        float rs0 = 0.f, rs1 = 0.f;
        #pragma unroll
        for (int nt = 0; nt < 4; nt++) {
            s[nt][0] = __expf(s[nt][0] - mn0);
            s[nt][1] = __expf(s[nt][1] - mn0);
            s[nt][2] = __expf(s[nt][2] - mn1);
            s[nt][3] = __expf(s[nt][3] - mn1);
            rs0 += s[nt][0] + s[nt][1];
            rs1 += s[nt][2] + s[nt][3];
        }
        rs0 += __shfl_xor_sync(0xffffffffu, rs0, 1);
        rs0 += __shfl_xor_sync(0xffffffffu, rs0, 2);
        rs1 += __shfl_xor_sync(0xffffffffu, rs1, 1);
        rs1 += __shfl_xor_sync(0xffffffffu, rs1, 2);
        l0 = l0 * al0 + rs0;
        l1 = l1 * al1 + rs1;
        #pragma unroll
        for (int nt = 0; nt < 8; nt++) {
            o[nt][0] *= al0; o[nt][1] *= al0;
            o[nt][2] *= al1; o[nt][3] *= al1;
        }

        // ---- stage P (per-warp rows; tf32-rounded through registers) ----
        #pragma unroll
        for (int nt = 0; nt < 4; nt++) {
            int c = nt * 8 + t * 2;
            *(float2*)&Ps[ri * 36 + c] =
                make_float2(f2tff(s[nt][0]), f2tff(s[nt][1]));
            *(float2*)&Ps[(ri + 8) * 36 + c] =
                make_float2(f2tff(s[nt][2]), f2tff(s[nt][3]));
        }
        __syncwarp();

        // ---- O += P V (16 x 64 per warp) ----
        #pragma unroll
        for (int kt = 0; kt < 4; kt++) {
            int ab = ri * 36 + kt * 8 + t;
            uint32_t a0 = __float_as_uint(Ps[ab]);
            uint32_t a1 = __float_as_uint(Ps[ab + 8 * 36]);
            uint32_t a2 = __float_as_uint(Ps[ab + 4]);
            uint32_t a3 = __float_as_uint(Ps[ab + 8 * 36 + 4]);
            #pragma unroll
            for (int nt = 0; nt < 8; nt++) {
                int bb = (nt * 8 + g) * 36 + kt * 8 + t;
                uint32_t b0 = __float_as_uint(V[bb]);
                uint32_t b1 = __float_as_uint(V[bb + 4]);
                mma_tf32(o[nt], a0, a1, a2, a3, b0, b1);
            }
        }
    }

    // ---- epilogue: normalize, transpose into Qs (own columns only), store ----
    float inv0 = 1.f / l0, inv1 = 1.f / l1;
    #pragma unroll
    for (int nt = 0; nt < 8; nt++) {
        int d = nt * 8 + t * 2;
        Qs[(d)     * 136 + ri]     = o[nt][0] * inv0;
        Qs[(d + 1) * 136 + ri]     = o[nt][1] * inv0;
        Qs[(d)     * 136 + ri + 8] = o[nt][2] * inv1;
        Qs[(d + 1) * 136 + ri + 8] = o[nt][3] * inv1;
    }
    __syncthreads();

    float* Og = out + ((size_t)b * E_DIM + h * HD) * N_TOK + i0;
    #pragma unroll
    for (int r = 0; r < 32; r++) {
        int idx = r * 256 + tid;
        int d = idx >> 7, i = idx & 127;
        Og[(size_t)d * N_TOK + i] = Qs[d * 136 + i];
    }
}

extern "C" void kernel_launch(void* const* d_in, const int* in_sizes, int n_in,
                              void* d_out, int out_size) {
    const float* query = (const float*)d_in[0];
    const float* key   = (const float*)d_in[1];
    const float* Wq    = (const float*)d_in[2];
    const float* bq    = (const float*)d_in[3];
    const float* Wk    = (const float*)d_in[4];
    const float* bk    = (const float*)d_in[5];
    const float* Wv    = (const float*)d_in[6];
    const float* bv    = (const float*)d_in[7];
    float* out = (float*)d_out;

    float *dTQ, *dTK, *dW;
    cudaGetSymbolAddress((void**)&dTQ, g_TQ);
    cudaGetSymbolAddress((void**)&dTK, g_TK);
    cudaGetSymbolAddress((void**)&dW,  g_W);

    const int nT4 = B_SZ * C_DIM * N_TOK / 4;     // 1M
    const int nW4 = E_DIM * C_DIM / 4;            // 64K
    round_kernel<<<2048, 256>>>(dTQ, query, nT4);
    round_kernel<<<2048, 256>>>(dTK, key,   nT4);
    round_kernel<<<512, 256>>>(dW,           Wq, nW4);
    round_kernel<<<512, 256>>>(dW + E_DIM * C_DIM,     Wk, nW4);
    round_kernel<<<512, 256>>>(dW + 2 * E_DIM * C_DIM, Wv, nW4);

    const int proj_smem = (4608 + 8704) * (int)sizeof(float);     // 53248
    cudaFuncSetAttribute(proj_kernel, cudaFuncAttributeMaxDynamicSharedMemorySize,
                         proj_smem);
    proj_kernel<<<dim3(N_TOK / 128, E_DIM / 64, 3 * B_SZ), 256, proj_smem>>>(
        bq, bk, bv);

    const int attn_smem = 23040 * (int)sizeof(float);             // 92160
    cudaFuncSetAttribute(attn_kernel, cudaFuncAttributeMaxDynamicSharedMemorySize,
                         attn_smem);
    attn_kernel<<<dim3(N_TOK / 128, NH, B_SZ), 256, attn_smem>>>(out);
}